// round 1
// baseline (speedup 1.0000x reference)
#include <cuda_runtime.h>
#include <math.h>

#define DM    1024
#define NH    16
#define DH    64
#define BATCH 2
#define SEQ   2048
#define MTOT  (BATCH*SEQ)     // 4096
#define BH    (BATCH*NH)      // 32

// Scratch (device globals: allocation-free contract)
__device__ float g_Q[BH*SEQ*DH];      // [b,h,s,d]
__device__ float g_K[BH*SEQ*DH];
__device__ float g_V[BH*SEQ*DH];
__device__ float g_attn[MTOT*DM];     // [b,s, h*64+d]

// ---------------------------------------------------------------------------
// Tiled fp32 GEMM: C[M=4096, N=1024] = A[M,K=1024] @ W[K,N] + bias[N]
// BM=64, BN=64, BK=32, 128 threads, 8x4 micro-tile per thread.
// OUT_BHSD=1: scatter output into [b,h,s,d] layout.
// ---------------------------------------------------------------------------
template<int OUT_BHSD>
__global__ __launch_bounds__(128)
void gemm_kernel(const float* __restrict__ A, const float* __restrict__ W,
                 const float* __restrict__ bias, float* __restrict__ C)
{
    __shared__ float Ash[32*68];   // transposed: Ash[k*68 + m]
    __shared__ float Bsh[32*68];   // natural:    Bsh[k*68 + n]

    const int tid = threadIdx.x;
    const int tx = tid & 15;       // 0..15 -> n
    const int ty = tid >> 4;       // 0..7  -> m
    const int n0 = blockIdx.x * 64;
    const int m0 = blockIdx.y * 64;

    float acc[8][4];
#pragma unroll
    for (int i = 0; i < 8; i++)
#pragma unroll
        for (int j = 0; j < 4; j++) acc[i][j] = 0.f;

    for (int k0 = 0; k0 < DM; k0 += 32) {
        // A tile: 64 rows x 32 k, float4 along k, store transposed
#pragma unroll
        for (int r = 0; r < 4; r++) {
            int q4  = tid + 128*r;
            int row = q4 >> 3;           // 0..63
            int c4  = q4 & 7;            // 0..7
            float4 v = *(const float4*)(A + (size_t)(m0+row)*DM + k0 + c4*4);
            Ash[(c4*4+0)*68 + row] = v.x;
            Ash[(c4*4+1)*68 + row] = v.y;
            Ash[(c4*4+2)*68 + row] = v.z;
            Ash[(c4*4+3)*68 + row] = v.w;
        }
        // B tile: 32 k x 64 n, float4 along n, natural layout
#pragma unroll
        for (int r = 0; r < 4; r++) {
            int q4  = tid + 128*r;
            int row = q4 >> 4;           // 0..31
            int c4  = q4 & 15;           // 0..15
            *(float4*)(Bsh + row*68 + c4*4) =
                *(const float4*)(W + (size_t)(k0+row)*DM + n0 + c4*4);
        }
        __syncthreads();

#pragma unroll 8
        for (int kk = 0; kk < 32; kk++) {
            float a[8], b[4];
            float4 a0 = *(const float4*)(Ash + kk*68 + ty*8);
            float4 a1 = *(const float4*)(Ash + kk*68 + ty*8 + 4);
            a[0]=a0.x; a[1]=a0.y; a[2]=a0.z; a[3]=a0.w;
            a[4]=a1.x; a[5]=a1.y; a[6]=a1.z; a[7]=a1.w;
            float4 b0 = *(const float4*)(Bsh + kk*68 + tx*4);
            b[0]=b0.x; b[1]=b0.y; b[2]=b0.z; b[3]=b0.w;
#pragma unroll
            for (int i = 0; i < 8; i++)
#pragma unroll
                for (int j = 0; j < 4; j++)
                    acc[i][j] = fmaf(a[i], b[j], acc[i][j]);
        }
        __syncthreads();
    }

#pragma unroll
    for (int i = 0; i < 8; i++) {
        int m = m0 + ty*8 + i;
#pragma unroll
        for (int j = 0; j < 4; j++) {
            int n = n0 + tx*4 + j;
            float v = acc[i][j] + bias[n];
            if (OUT_BHSD) {
                int b = m >> 11, s = m & (SEQ-1);
                int h = n >> 6,  d = n & (DH-1);
                C[(((size_t)(b*NH + h))*SEQ + s)*DH + d] = v;
            } else {
                C[(size_t)m*DM + n] = v;
            }
        }
    }
}

// ---------------------------------------------------------------------------
// Partial RoPE in-place on Q,K in [b,h,s,d]: rotate dims [0:16) (half=8)
// ---------------------------------------------------------------------------
__global__ void rope_kernel(float* __restrict__ Q, float* __restrict__ K)
{
    int idx = blockIdx.x*blockDim.x + threadIdx.x;
    const int total = BH*SEQ*8;
    if (idx >= total) return;
    int i   = idx & 7;
    int row = idx >> 3;          // (b*NH+h)*SEQ + s
    int s   = row & (SEQ-1);

    float inv_freq = powf(10000.0f, -(float)i * 0.125f);
    float ang = (float)s * inv_freq;
    float c, sn;
    sincosf(ang, &sn, &c);

    float* q = Q + (size_t)row*DH;
    float t1 = q[i], t2 = q[i+8];
    q[i]   = t1*c - t2*sn;
    q[i+8] = t1*sn + t2*c;

    float* k = K + (size_t)row*DH;
    t1 = k[i]; t2 = k[i+8];
    k[i]   = t1*c - t2*sn;
    k[i+8] = t1*sn + t2*c;
}

// ---------------------------------------------------------------------------
// Causal flash attention, fp32. One CTA per (b,h, 64-query tile).
// 128 threads, 8x4 micro-tiles for both QK^T and PV. Online softmax.
// Output written to g_attn in [b,s, h*64+d] layout.
// ---------------------------------------------------------------------------
#define ATTN_SMEM_FLOATS (4*64*68 + 3*64)

__global__ __launch_bounds__(128)
void attn_kernel(const float* __restrict__ Q, const float* __restrict__ K,
                 const float* __restrict__ V, float* __restrict__ attn)
{
    extern __shared__ float sm[];
    float* Qs   = sm;              // transposed: Qs[d*68 + m_row]
    float* Ks   = Qs + 64*68;      // transposed: Ks[d*68 + n_row]
    float* Vs   = Ks + 64*68;      // natural:    Vs[n_row*68 + c]
    float* Ss   = Vs + 64*68;      // natural:    Ss[m_row*68 + n_col]
    float* m_sh = Ss + 64*68;      // [64]
    float* l_sh = m_sh + 64;       // [64]
    float* a_sh = l_sh + 64;       // [64]

    const int tid = threadIdx.x;
    const int tx = tid & 15;       // key / dim cols
    const int ty = tid >> 4;       // query rows
    const int bh = blockIdx.y;
    const int m0 = blockIdx.x * 64;

    const float* Qg = Q + (size_t)bh*SEQ*DH;
    const float* Kg = K + (size_t)bh*SEQ*DH;
    const float* Vg = V + (size_t)bh*SEQ*DH;

    // Load Q tile (64 rows x 64 d), transposed into smem
#pragma unroll
    for (int r = 0; r < 8; r++) {
        int q4  = tid + 128*r;
        int row = q4 >> 4;          // 0..63
        int c4  = q4 & 15;          // 0..15
        float4 v = *(const float4*)(Qg + (size_t)(m0+row)*DH + c4*4);
        Qs[(c4*4+0)*68 + row] = v.x;
        Qs[(c4*4+1)*68 + row] = v.y;
        Qs[(c4*4+2)*68 + row] = v.z;
        Qs[(c4*4+3)*68 + row] = v.w;
    }
    if (tid < 64) { m_sh[tid] = -1e30f; l_sh[tid] = 0.f; }

    float o[8][4];
#pragma unroll
    for (int i = 0; i < 8; i++)
#pragma unroll
        for (int j = 0; j < 4; j++) o[i][j] = 0.f;

    __syncthreads();

    for (int n0 = 0; n0 <= m0; n0 += 64) {
        // Load K (transposed) and V (natural) tiles
#pragma unroll
        for (int r = 0; r < 8; r++) {
            int q4  = tid + 128*r;
            int row = q4 >> 4;
            int c4  = q4 & 15;
            float4 kv = *(const float4*)(Kg + (size_t)(n0+row)*DH + c4*4);
            Ks[(c4*4+0)*68 + row] = kv.x;
            Ks[(c4*4+1)*68 + row] = kv.y;
            Ks[(c4*4+2)*68 + row] = kv.z;
            Ks[(c4*4+3)*68 + row] = kv.w;
            *(float4*)(Vs + row*68 + c4*4) =
                *(const float4*)(Vg + (size_t)(n0+row)*DH + c4*4);
        }
        __syncthreads();

        // S = Q @ K^T  (64x64x64)
        float s[8][4];
#pragma unroll
        for (int i = 0; i < 8; i++)
#pragma unroll
            for (int j = 0; j < 4; j++) s[i][j] = 0.f;

#pragma unroll 8
        for (int d = 0; d < 64; d++) {
            float a[8], b[4];
            float4 a0 = *(const float4*)(Qs + d*68 + ty*8);
            float4 a1 = *(const float4*)(Qs + d*68 + ty*8 + 4);
            a[0]=a0.x; a[1]=a0.y; a[2]=a0.z; a[3]=a0.w;
            a[4]=a1.x; a[5]=a1.y; a[6]=a1.z; a[7]=a1.w;
            float4 b0 = *(const float4*)(Ks + d*68 + tx*4);
            b[0]=b0.x; b[1]=b0.y; b[2]=b0.z; b[3]=b0.w;
#pragma unroll
            for (int i = 0; i < 8; i++)
#pragma unroll
                for (int j = 0; j < 4; j++)
                    s[i][j] = fmaf(a[i], b[j], s[i][j]);
        }

        // scale + causal mask, stage S into smem
        const float scale = 0.125f;   // 1/sqrt(64)
#pragma unroll
        for (int i = 0; i < 8; i++) {
            int qrow = m0 + ty*8 + i;
            float t0 = s[i][0]*scale, t1 = s[i][1]*scale,
                  t2 = s[i][2]*scale, t3 = s[i][3]*scale;
            int kc = n0 + tx*4;
            if (kc+0 > qrow) t0 = -1e30f;
            if (kc+1 > qrow) t1 = -1e30f;
            if (kc+2 > qrow) t2 = -1e30f;
            if (kc+3 > qrow) t3 = -1e30f;
            *(float4*)(Ss + (ty*8+i)*68 + tx*4) = make_float4(t0,t1,t2,t3);
        }
        __syncthreads();

        // Online softmax row pass (one thread per query row)
        if (tid < 64) {
            int row = tid;
            float mold = m_sh[row];
            float mx = mold;
            float* srow = Ss + row*68;
#pragma unroll 8
            for (int c = 0; c < 64; c++) mx = fmaxf(mx, srow[c]);
            float alpha = __expf(mold - mx);
            float sum = 0.f;
#pragma unroll 8
            for (int c = 0; c < 64; c++) {
                float p = __expf(srow[c] - mx);
                srow[c] = p;
                sum += p;
            }
            l_sh[row] = l_sh[row]*alpha + sum;
            m_sh[row] = mx;
            a_sh[row] = alpha;
        }
        __syncthreads();

        // Rescale accumulators, then O += P @ V
#pragma unroll
        for (int i = 0; i < 8; i++) {
            float al = a_sh[ty*8 + i];
#pragma unroll
            for (int j = 0; j < 4; j++) o[i][j] *= al;
        }
#pragma unroll 8
        for (int n = 0; n < 64; n++) {
            float4 v4 = *(const float4*)(Vs + n*68 + tx*4);
            float b[4] = {v4.x, v4.y, v4.z, v4.w};
            float p[8];
#pragma unroll
            for (int i = 0; i < 8; i++) p[i] = Ss[(ty*8+i)*68 + n];
#pragma unroll
            for (int i = 0; i < 8; i++)
#pragma unroll
                for (int j = 0; j < 4; j++)
                    o[i][j] = fmaf(p[i], b[j], o[i][j]);
        }
        __syncthreads();
    }

    // Epilogue: normalize by l, store into [b,s,h*64+d] layout
    const int b = bh >> 4, h = bh & 15;
#pragma unroll
    for (int i = 0; i < 8; i++) {
        int row = ty*8 + i;
        float inv_l = 1.f / l_sh[row];
        float4 ov = make_float4(o[i][0]*inv_l, o[i][1]*inv_l,
                                o[i][2]*inv_l, o[i][3]*inv_l);
        *(float4*)(attn + ((size_t)(b*SEQ + m0 + row))*DM + h*DH + tx*4) = ov;
    }
}

// ---------------------------------------------------------------------------
extern "C" void kernel_launch(void* const* d_in, const int* in_sizes, int n_in,
                              void* d_out, int out_size)
{
    const float* x  = (const float*)d_in[0];
    const float* Wq = (const float*)d_in[1];
    const float* bq = (const float*)d_in[2];
    const float* Wk = (const float*)d_in[3];
    const float* bk = (const float*)d_in[4];
    const float* Wv = (const float*)d_in[5];
    const float* bv = (const float*)d_in[6];
    const float* Wo = (const float*)d_in[7];
    const float* bo = (const float*)d_in[8];
    float* out = (float*)d_out;

    float *Qp, *Kp, *Vp, *Ap;
    cudaGetSymbolAddress((void**)&Qp, g_Q);
    cudaGetSymbolAddress((void**)&Kp, g_K);
    cudaGetSymbolAddress((void**)&Vp, g_V);
    cudaGetSymbolAddress((void**)&Ap, g_attn);

    const int attn_smem = ATTN_SMEM_FLOATS * (int)sizeof(float);  // 70400 B
    cudaFuncSetAttribute(attn_kernel,
                         cudaFuncAttributeMaxDynamicSharedMemorySize, attn_smem);

    dim3 gemm_grid(DM/64, MTOT/64);   // (16, 64)

    gemm_kernel<1><<<gemm_grid, 128>>>(x, Wq, bq, Qp);
    gemm_kernel<1><<<gemm_grid, 128>>>(x, Wk, bk, Kp);
    gemm_kernel<1><<<gemm_grid, 128>>>(x, Wv, bv, Vp);

    rope_kernel<<<(BH*SEQ*8 + 255)/256, 256>>>(Qp, Kp);

    attn_kernel<<<dim3(SEQ/64, BH), 128, attn_smem>>>(Qp, Kp, Vp, Ap);

    gemm_kernel<0><<<gemm_grid, 128>>>(Ap, Wo, bo, out);
}

// round 5
// speedup vs baseline: 1.4560x; 1.4560x over previous
#include <cuda_runtime.h>
#include <cuda_bf16.h>
#include <cstdint>
#include <math.h>

#define DM    1024
#define NH    16
#define DH    64
#define BATCH 2
#define SEQ   2048
#define MTOT  (BATCH*SEQ)     // 4096
#define BH    (BATCH*NH)      // 32

// ---------------- scratch (device globals; allocation-free contract) -------
__device__ __align__(128) float g_Q[BH*SEQ*DH];      // [b,h,s,d]
__device__ __align__(128) float g_K[BH*SEQ*DH];
__device__ __align__(128) float g_V[BH*SEQ*DH];
__device__ __align__(128) float g_attn[MTOT*DM];     // [b,s, h*64+d] == [M,K]

__device__ __align__(128) __nv_bfloat16 g_xb[MTOT*DM];
__device__ __align__(128) __nv_bfloat16 g_xs[MTOT*DM];
__device__ __align__(128) __nv_bfloat16 g_ab[MTOT*DM];
__device__ __align__(128) __nv_bfloat16 g_as[MTOT*DM];
__device__ __align__(128) __nv_bfloat16 g_WbT[4*DM*DM];   // [N,K] per matrix
__device__ __align__(128) __nv_bfloat16 g_WsT[4*DM*DM];

// ---------------- PTX helpers (sm_80-compatible only!) ----------------------
__device__ __forceinline__ uint32_t smem_u32(const void* p) {
    uint32_t a;
    asm("{ .reg .u64 t; cvta.to.shared.u64 t, %1; cvt.u32.u64 %0, t; }" : "=r"(a) : "l"(p));
    return a;
}
__device__ __forceinline__ void cp_async16(uint32_t dst, const void* src) {
    asm volatile("cp.async.cg.shared.global [%0], [%1], 16;" :: "r"(dst), "l"(src));
}
#define CP_COMMIT() asm volatile("cp.async.commit_group;" ::: "memory")
#define CP_WAIT1()  asm volatile("cp.async.wait_group 1;" ::: "memory")

__device__ __forceinline__ void ldmx4(uint32_t& r0, uint32_t& r1, uint32_t& r2,
                                      uint32_t& r3, uint32_t addr) {
    asm volatile("ldmatrix.sync.aligned.m8n8.x4.shared.b16 {%0,%1,%2,%3}, [%4];"
                 : "=r"(r0), "=r"(r1), "=r"(r2), "=r"(r3) : "r"(addr));
}
__device__ __forceinline__ void mma_bf16(float* d, uint32_t a0, uint32_t a1,
                                         uint32_t a2, uint32_t a3,
                                         uint32_t b0, uint32_t b1) {
    asm volatile(
        "mma.sync.aligned.m16n8k16.row.col.f32.bf16.bf16.f32 "
        "{%0,%1,%2,%3}, {%4,%5,%6,%7}, {%8,%9}, {%0,%1,%2,%3};"
        : "+f"(d[0]), "+f"(d[1]), "+f"(d[2]), "+f"(d[3])
        : "r"(a0), "r"(a1), "r"(a2), "r"(a3), "r"(b0), "r"(b1));
}

// ---------------- split kernels ---------------------------------------------
__global__ void split_bf16_kernel(const float* __restrict__ in,
                                  __nv_bfloat16* __restrict__ big,
                                  __nv_bfloat16* __restrict__ small, int n)
{
    int i = blockIdx.x * blockDim.x + threadIdx.x;
    if (i >= n) return;
    float v = in[i];
    __nv_bfloat16 b = __float2bfloat16(v);
    big[i]   = b;
    small[i] = __float2bfloat16(v - __bfloat162float(b));
}

// W [K,N] row-major -> W^T big/small bf16 [N,K] row-major
__global__ void split_transpose_kernel(const float* __restrict__ W,
                                       __nv_bfloat16* __restrict__ bigT,
                                       __nv_bfloat16* __restrict__ smallT)
{
    __shared__ __nv_bfloat16 tb[32][33];
    __shared__ __nv_bfloat16 ts[32][33];
    int n0 = blockIdx.x * 32, k0 = blockIdx.y * 32;
#pragma unroll
    for (int rr = 0; rr < 4; rr++) {
        int r = threadIdx.y + rr * 8;
        float v = W[(size_t)(k0 + r) * DM + n0 + threadIdx.x];
        __nv_bfloat16 b = __float2bfloat16(v);
        tb[r][threadIdx.x] = b;
        ts[r][threadIdx.x] = __float2bfloat16(v - __bfloat162float(b));
    }
    __syncthreads();
#pragma unroll
    for (int rr = 0; rr < 4; rr++) {
        int r = threadIdx.y + rr * 8;   // output row (n)
        bigT  [(size_t)(n0 + r) * DM + k0 + threadIdx.x] = tb[threadIdx.x][r];
        smallT[(size_t)(n0 + r) * DM + k0 + threadIdx.x] = ts[threadIdx.x][r];
    }
}

// ---------------- mma.sync bf16 GEMM (3xBF16) --------------------------------
// C[M=4096, N=1024] = A @ B^T + bias
// A big/small: [M,K] bf16 row-major; B big/small: [N,K] bf16 row-major.
// CTA tile 128x128, BK=32, 8 warps (4 in m x 2 in n), warp tile 32x64.
#define BM 128
#define BN 128
#define KC 32
#define NCHUNK (DM/KC)

// SMEM: per tile 128 rows x 80B (32 bf16 + 16B pad) = 10240 B.
#define ROWB 80
#define TILE_B (128*ROWB)
#define OFF_AB 0
#define OFF_AS (1*TILE_B)
#define OFF_BB (2*TILE_B)
#define OFF_BS (3*TILE_B)
#define STAGE_B (4*TILE_B)        // 40960
#define GEMM_SMEM (2*STAGE_B)     // 81920

__device__ __forceinline__ void load_chunk(
    const __nv_bfloat16* __restrict__ Ab, const __nv_bfloat16* __restrict__ As,
    const __nv_bfloat16* __restrict__ Bb, const __nv_bfloat16* __restrict__ Bs,
    int m0, int n0, int k0, uint32_t buf, int tid)
{
    // each tile: 128 rows x 4 chunks of 16B = 512 cp.async; 256 threads -> 2 iters
    const __nv_bfloat16* srcs[4] = {
        Ab + (size_t)m0 * DM + k0,  As + (size_t)m0 * DM + k0,
        Bb + (size_t)n0 * DM + k0,  Bs + (size_t)n0 * DM + k0 };
    const uint32_t offs[4] = { OFF_AB, OFF_AS, OFF_BB, OFF_BS };
#pragma unroll
    for (int t = 0; t < 4; t++) {
#pragma unroll
        for (int i = 0; i < 2; i++) {
            int idx = i * 256 + tid;        // 0..511
            int row = idx >> 2, c = idx & 3;
            cp_async16(buf + offs[t] + row * ROWB + c * 16,
                       srcs[t] + (size_t)row * DM + c * 8);
        }
    }
}

template<int OUT_BHSD>
__global__ __launch_bounds__(256)
void gemm_mma(const __nv_bfloat16* __restrict__ Ab, const __nv_bfloat16* __restrict__ As,
              const __nv_bfloat16* __restrict__ Bb, const __nv_bfloat16* __restrict__ Bs,
              const float* __restrict__ bias, float* __restrict__ C)
{
    extern __shared__ char smem[];
    const uint32_t sbase = smem_u32(smem);
    const int tid  = threadIdx.x;
    const int wid  = tid >> 5;
    const int lane = tid & 31;
    const int warp_m = wid & 3;        // 0..3 -> 32-row slice
    const int warp_n = wid >> 2;       // 0..1 -> 64-col slice
    const int m0 = blockIdx.y * BM;
    const int n0 = blockIdx.x * BN;

    float acc[2][8][4];
#pragma unroll
    for (int i = 0; i < 2; i++)
#pragma unroll
        for (int j = 0; j < 8; j++)
#pragma unroll
            for (int t = 0; t < 4; t++) acc[i][j][t] = 0.f;

    // ldmatrix address components (within-stage offsets)
    const int a_r  = lane & 15;
    const int a_kh = (lane >> 4) * 8;
    const int b_g  = lane >> 3;
    const int b_lr = lane & 7;
    const int b_n  = (b_g >> 1) * 8 + b_lr;   // 0..15 within pair
    const int b_kh = (b_g & 1) * 8;

    // prologue
    load_chunk(Ab, As, Bb, Bs, m0, n0, 0,  sbase,           tid); CP_COMMIT();
    load_chunk(Ab, As, Bb, Bs, m0, n0, KC, sbase + STAGE_B, tid); CP_COMMIT();

    for (int c = 0; c < NCHUNK; c++) {
        CP_WAIT1();
        __syncthreads();
        const uint32_t buf = sbase + (uint32_t)(c & 1) * STAGE_B;

#pragma unroll
        for (int ks = 0; ks < 2; ks++) {            // two k16 steps per chunk
            const int k16 = ks * 16;
            uint32_t ab[2][4], asm_[2][4];
#pragma unroll
            for (int i = 0; i < 2; i++) {
                uint32_t arow = (uint32_t)(warp_m * 32 + i * 16 + a_r);
                uint32_t aoff = arow * ROWB + (uint32_t)((k16 + a_kh) >> 3) * 16;
                ldmx4(ab[i][0],  ab[i][1],  ab[i][2],  ab[i][3],  buf + OFF_AB + aoff);
                ldmx4(asm_[i][0], asm_[i][1], asm_[i][2], asm_[i][3], buf + OFF_AS + aoff);
            }
#pragma unroll
            for (int jp = 0; jp < 4; jp++) {
                uint32_t brow = (uint32_t)(warp_n * 64 + jp * 16 + b_n);
                uint32_t boff = brow * ROWB + (uint32_t)((k16 + b_kh) >> 3) * 16;
                uint32_t bb0, bb1, bb2, bb3, bs0, bs1, bs2, bs3;
                ldmx4(bb0, bb1, bb2, bb3, buf + OFF_BB + boff);
                ldmx4(bs0, bs1, bs2, bs3, buf + OFF_BS + boff);
#pragma unroll
                for (int i = 0; i < 2; i++) {
                    mma_bf16(acc[i][jp*2],   ab[i][0], ab[i][1], ab[i][2], ab[i][3], bb0, bb1);
                    mma_bf16(acc[i][jp*2],   ab[i][0], ab[i][1], ab[i][2], ab[i][3], bs0, bs1);
                    mma_bf16(acc[i][jp*2],   asm_[i][0], asm_[i][1], asm_[i][2], asm_[i][3], bb0, bb1);
                    mma_bf16(acc[i][jp*2+1], ab[i][0], ab[i][1], ab[i][2], ab[i][3], bb2, bb3);
                    mma_bf16(acc[i][jp*2+1], ab[i][0], ab[i][1], ab[i][2], ab[i][3], bs2, bs3);
                    mma_bf16(acc[i][jp*2+1], asm_[i][0], asm_[i][1], asm_[i][2], asm_[i][3], bb2, bb3);
                }
            }
        }
        __syncthreads();
        if (c + 2 < NCHUNK)
            load_chunk(Ab, As, Bb, Bs, m0, n0, (c + 2) * KC, buf, tid);
        CP_COMMIT();
    }

    // epilogue
    const int gr = lane >> 2;          // 0..7
    const int tc = lane & 3;           // 0..3
#pragma unroll
    for (int i = 0; i < 2; i++) {
#pragma unroll
        for (int j = 0; j < 8; j++) {
            int col = n0 + warp_n * 64 + j * 8 + tc * 2;
            float b0 = __ldg(bias + col), b1 = __ldg(bias + col + 1);
#pragma unroll
            for (int h = 0; h < 2; h++) {
                int row = m0 + warp_m * 32 + i * 16 + gr + h * 8;
                float2 v = make_float2(acc[i][j][h*2] + b0, acc[i][j][h*2+1] + b1);
                if (OUT_BHSD) {
                    int bb = row >> 11, s = row & (SEQ - 1);
                    int hh = col >> 6,  d = col & (DH - 1);
                    *(float2*)(C + (((size_t)(bb * NH + hh)) * SEQ + s) * DH + d) = v;
                } else {
                    *(float2*)(C + (size_t)row * DM + col) = v;
                }
            }
        }
    }
}

// ---------------------------------------------------------------------------
// Partial RoPE in-place on Q,K in [b,h,s,d]: rotate dims [0:16) (half=8)
// ---------------------------------------------------------------------------
__global__ void rope_kernel(float* __restrict__ Q, float* __restrict__ K)
{
    int idx = blockIdx.x*blockDim.x + threadIdx.x;
    const int total = BH*SEQ*8;
    if (idx >= total) return;
    int i   = idx & 7;
    int row = idx >> 3;
    int s   = row & (SEQ-1);

    float inv_freq = powf(10000.0f, -(float)i * 0.125f);
    float ang = (float)s * inv_freq;
    float c, sn;
    sincosf(ang, &sn, &c);

    float* q = Q + (size_t)row*DH;
    float t1 = q[i], t2 = q[i+8];
    q[i]   = t1*c - t2*sn;
    q[i+8] = t1*sn + t2*c;

    float* k = K + (size_t)row*DH;
    t1 = k[i]; t2 = k[i+8];
    k[i]   = t1*c - t2*sn;
    k[i+8] = t1*sn + t2*c;
}

// ---------------------------------------------------------------------------
// Causal flash attention, fp32 SIMT (unchanged; known-good).
// ---------------------------------------------------------------------------
#define ATTN_SMEM_FLOATS (4*64*68 + 3*64)

__global__ __launch_bounds__(128)
void attn_kernel(const float* __restrict__ Q, const float* __restrict__ K,
                 const float* __restrict__ V, float* __restrict__ attn)
{
    extern __shared__ float sm[];
    float* Qs   = sm;
    float* Ks   = Qs + 64*68;
    float* Vs   = Ks + 64*68;
    float* Ss   = Vs + 64*68;
    float* m_sh = Ss + 64*68;
    float* l_sh = m_sh + 64;
    float* a_sh = l_sh + 64;

    const int tid = threadIdx.x;
    const int tx = tid & 15;
    const int ty = tid >> 4;
    const int bh = blockIdx.y;
    const int m0 = blockIdx.x * 64;

    const float* Qg = Q + (size_t)bh*SEQ*DH;
    const float* Kg = K + (size_t)bh*SEQ*DH;
    const float* Vg = V + (size_t)bh*SEQ*DH;

#pragma unroll
    for (int r = 0; r < 8; r++) {
        int q4  = tid + 128*r;
        int row = q4 >> 4;
        int c4  = q4 & 15;
        float4 v = *(const float4*)(Qg + (size_t)(m0+row)*DH + c4*4);
        Qs[(c4*4+0)*68 + row] = v.x;
        Qs[(c4*4+1)*68 + row] = v.y;
        Qs[(c4*4+2)*68 + row] = v.z;
        Qs[(c4*4+3)*68 + row] = v.w;
    }
    if (tid < 64) { m_sh[tid] = -1e30f; l_sh[tid] = 0.f; }

    float o[8][4];
#pragma unroll
    for (int i = 0; i < 8; i++)
#pragma unroll
        for (int j = 0; j < 4; j++) o[i][j] = 0.f;

    __syncthreads();

    for (int n0 = 0; n0 <= m0; n0 += 64) {
#pragma unroll
        for (int r = 0; r < 8; r++) {
            int q4  = tid + 128*r;
            int row = q4 >> 4;
            int c4  = q4 & 15;
            float4 kv = *(const float4*)(Kg + (size_t)(n0+row)*DH + c4*4);
            Ks[(c4*4+0)*68 + row] = kv.x;
            Ks[(c4*4+1)*68 + row] = kv.y;
            Ks[(c4*4+2)*68 + row] = kv.z;
            Ks[(c4*4+3)*68 + row] = kv.w;
            *(float4*)(Vs + row*68 + c4*4) =
                *(const float4*)(Vg + (size_t)(n0+row)*DH + c4*4);
        }
        __syncthreads();

        float s[8][4];
#pragma unroll
        for (int i = 0; i < 8; i++)
#pragma unroll
            for (int j = 0; j < 4; j++) s[i][j] = 0.f;

#pragma unroll 8
        for (int d = 0; d < 64; d++) {
            float a[8], b[4];
            float4 a0 = *(const float4*)(Qs + d*68 + ty*8);
            float4 a1 = *(const float4*)(Qs + d*68 + ty*8 + 4);
            a[0]=a0.x; a[1]=a0.y; a[2]=a0.z; a[3]=a0.w;
            a[4]=a1.x; a[5]=a1.y; a[6]=a1.z; a[7]=a1.w;
            float4 b0 = *(const float4*)(Ks + d*68 + tx*4);
            b[0]=b0.x; b[1]=b0.y; b[2]=b0.z; b[3]=b0.w;
#pragma unroll
            for (int i = 0; i < 8; i++)
#pragma unroll
                for (int j = 0; j < 4; j++)
                    s[i][j] = fmaf(a[i], b[j], s[i][j]);
        }

        const float scale = 0.125f;
#pragma unroll
        for (int i = 0; i < 8; i++) {
            int qrow = m0 + ty*8 + i;
            float t0 = s[i][0]*scale, t1 = s[i][1]*scale,
                  t2 = s[i][2]*scale, t3 = s[i][3]*scale;
            int kc = n0 + tx*4;
            if (kc+0 > qrow) t0 = -1e30f;
            if (kc+1 > qrow) t1 = -1e30f;
            if (kc+2 > qrow) t2 = -1e30f;
            if (kc+3 > qrow) t3 = -1e30f;
            *(float4*)(Ss + (ty*8+i)*68 + tx*4) = make_float4(t0,t1,t2,t3);
        }
        __syncthreads();

        if (tid < 64) {
            int row = tid;
            float mold = m_sh[row];
            float mx = mold;
            float* srow = Ss + row*68;
#pragma unroll 8
            for (int c = 0; c < 64; c++) mx = fmaxf(mx, srow[c]);
            float alpha = __expf(mold - mx);
            float sum = 0.f;
#pragma unroll 8
            for (int c = 0; c < 64; c++) {
                float p = __expf(srow[c] - mx);
                srow[c] = p;
                sum += p;
            }
            l_sh[row] = l_sh[row]*alpha + sum;
            m_sh[row] = mx;
            a_sh[row] = alpha;
        }
        __syncthreads();

#pragma unroll
        for (int i = 0; i < 8; i++) {
            float al = a_sh[ty*8 + i];
#pragma unroll
            for (int j = 0; j < 4; j++) o[i][j] *= al;
        }
#pragma unroll 8
        for (int n = 0; n < 64; n++) {
            float4 v4 = *(const float4*)(Vs + n*68 + tx*4);
            float b[4] = {v4.x, v4.y, v4.z, v4.w};
            float p[8];
#pragma unroll
            for (int i = 0; i < 8; i++) p[i] = Ss[(ty*8+i)*68 + n];
#pragma unroll
            for (int i = 0; i < 8; i++)
#pragma unroll
                for (int j = 0; j < 4; j++)
                    o[i][j] = fmaf(p[i], b[j], o[i][j]);
        }
        __syncthreads();
    }

    const int b = bh >> 4, h = bh & 15;
#pragma unroll
    for (int i = 0; i < 8; i++) {
        int row = ty*8 + i;
        float inv_l = 1.f / l_sh[row];
        float4 ov = make_float4(o[i][0]*inv_l, o[i][1]*inv_l,
                                o[i][2]*inv_l, o[i][3]*inv_l);
        *(float4*)(attn + ((size_t)(b*SEQ + m0 + row))*DM + h*DH + tx*4) = ov;
    }
}

// ---------------------------------------------------------------------------
extern "C" void kernel_launch(void* const* d_in, const int* in_sizes, int n_in,
                              void* d_out, int out_size)
{
    const float* x  = (const float*)d_in[0];
    const float* Wq = (const float*)d_in[1];
    const float* bq = (const float*)d_in[2];
    const float* Wk = (const float*)d_in[3];
    const float* bk = (const float*)d_in[4];
    const float* Wv = (const float*)d_in[5];
    const float* bv = (const float*)d_in[6];
    const float* Wo = (const float*)d_in[7];
    const float* bo = (const float*)d_in[8];
    float* out = (float*)d_out;

    float *Qp, *Kp, *Vp, *Ap;
    __nv_bfloat16 *xb, *xs, *ab, *as, *WbT, *WsT;
    cudaGetSymbolAddress((void**)&Qp, g_Q);
    cudaGetSymbolAddress((void**)&Kp, g_K);
    cudaGetSymbolAddress((void**)&Vp, g_V);
    cudaGetSymbolAddress((void**)&Ap, g_attn);
    cudaGetSymbolAddress((void**)&xb, g_xb);
    cudaGetSymbolAddress((void**)&xs, g_xs);
    cudaGetSymbolAddress((void**)&ab, g_ab);
    cudaGetSymbolAddress((void**)&as, g_as);
    cudaGetSymbolAddress((void**)&WbT, g_WbT);
    cudaGetSymbolAddress((void**)&WsT, g_WsT);

    const int attn_smem = ATTN_SMEM_FLOATS * (int)sizeof(float);
    cudaFuncSetAttribute(attn_kernel,
                         cudaFuncAttributeMaxDynamicSharedMemorySize, attn_smem);
    cudaFuncSetAttribute(gemm_mma<0>,
                         cudaFuncAttributeMaxDynamicSharedMemorySize, GEMM_SMEM);
    cudaFuncSetAttribute(gemm_mma<1>,
                         cudaFuncAttributeMaxDynamicSharedMemorySize, GEMM_SMEM);

    const int WSZ = DM * DM;

    // splits
    split_bf16_kernel<<<(MTOT*DM + 255)/256, 256>>>(x, xb, xs, MTOT*DM);
    dim3 tgrid(DM/32, DM/32), tblk(32, 8);
    split_transpose_kernel<<<tgrid, tblk>>>(Wq, WbT + 0*WSZ, WsT + 0*WSZ);
    split_transpose_kernel<<<tgrid, tblk>>>(Wk, WbT + 1*WSZ, WsT + 1*WSZ);
    split_transpose_kernel<<<tgrid, tblk>>>(Wv, WbT + 2*WSZ, WsT + 2*WSZ);
    split_transpose_kernel<<<tgrid, tblk>>>(Wo, WbT + 3*WSZ, WsT + 3*WSZ);

    // projections (mma.sync bf16, 3xBF16)
    dim3 ggrid(DM/BN, MTOT/BM);   // (8, 32)
    gemm_mma<1><<<ggrid, 256, GEMM_SMEM>>>(xb, xs, WbT + 0*WSZ, WsT + 0*WSZ, bq, Qp);
    gemm_mma<1><<<ggrid, 256, GEMM_SMEM>>>(xb, xs, WbT + 1*WSZ, WsT + 1*WSZ, bk, Kp);
    gemm_mma<1><<<ggrid, 256, GEMM_SMEM>>>(xb, xs, WbT + 2*WSZ, WsT + 2*WSZ, bv, Vp);

    rope_kernel<<<(BH*SEQ*8 + 255)/256, 256>>>(Qp, Kp);

    attn_kernel<<<dim3(SEQ/64, BH), 128, attn_smem>>>(Qp, Kp, Vp, Ap);

    split_bf16_kernel<<<(MTOT*DM + 255)/256, 256>>>(Ap, ab, as, MTOT*DM);
    gemm_mma<0><<<ggrid, 256, GEMM_SMEM>>>(ab, as, WbT + 3*WSZ, WsT + 3*WSZ, bo, out);
}

// round 7
// speedup vs baseline: 2.4051x; 1.6518x over previous
#include <cuda_runtime.h>
#include <cuda_bf16.h>
#include <cstdint>
#include <math.h>

#define DM    1024
#define NH    16
#define DH    64
#define BATCH 2
#define SEQ   2048
#define MTOT  (BATCH*SEQ)     // 4096
#define BH    (BATCH*NH)      // 32

// ---------------- scratch (device globals; allocation-free contract) -------
__device__ __align__(128) float g_Q[BH*SEQ*DH];      // [b,h,s,d]
__device__ __align__(128) float g_K[BH*SEQ*DH];
__device__ __align__(128) float g_V[BH*SEQ*DH];
__device__ __align__(128) float g_attn[MTOT*DM];     // [b,s, h*64+d] == [M,K]

__device__ __align__(128) __nv_bfloat16 g_xb[MTOT*DM];
__device__ __align__(128) __nv_bfloat16 g_xs[MTOT*DM];
__device__ __align__(128) __nv_bfloat16 g_ab[MTOT*DM];
__device__ __align__(128) __nv_bfloat16 g_as[MTOT*DM];
__device__ __align__(128) __nv_bfloat16 g_WbT[4*DM*DM];   // [N,K] per matrix
__device__ __align__(128) __nv_bfloat16 g_WsT[4*DM*DM];

// attention operand splits (bf16, [b,h,s,d])
__device__ __align__(128) __nv_bfloat16 g_Qb[BH*SEQ*DH];
__device__ __align__(128) __nv_bfloat16 g_Qs[BH*SEQ*DH];
__device__ __align__(128) __nv_bfloat16 g_Kb[BH*SEQ*DH];
__device__ __align__(128) __nv_bfloat16 g_Ks[BH*SEQ*DH];
__device__ __align__(128) __nv_bfloat16 g_Vb[BH*SEQ*DH];
__device__ __align__(128) __nv_bfloat16 g_Vs[BH*SEQ*DH];

// ---------------- PTX helpers (sm_80-compatible only!) ----------------------
__device__ __forceinline__ uint32_t smem_u32(const void* p) {
    uint32_t a;
    asm("{ .reg .u64 t; cvta.to.shared.u64 t, %1; cvt.u32.u64 %0, t; }" : "=r"(a) : "l"(p));
    return a;
}
__device__ __forceinline__ void cp_async16(uint32_t dst, const void* src) {
    asm volatile("cp.async.cg.shared.global [%0], [%1], 16;" :: "r"(dst), "l"(src));
}
#define CP_COMMIT() asm volatile("cp.async.commit_group;" ::: "memory")
#define CP_WAIT1()  asm volatile("cp.async.wait_group 1;" ::: "memory")

__device__ __forceinline__ void ldmx4(uint32_t& r0, uint32_t& r1, uint32_t& r2,
                                      uint32_t& r3, uint32_t addr) {
    asm volatile("ldmatrix.sync.aligned.m8n8.x4.shared.b16 {%0,%1,%2,%3}, [%4];"
                 : "=r"(r0), "=r"(r1), "=r"(r2), "=r"(r3) : "r"(addr));
}
__device__ __forceinline__ void ldmx4t(uint32_t& r0, uint32_t& r1, uint32_t& r2,
                                       uint32_t& r3, uint32_t addr) {
    asm volatile("ldmatrix.sync.aligned.m8n8.x4.trans.shared.b16 {%0,%1,%2,%3}, [%4];"
                 : "=r"(r0), "=r"(r1), "=r"(r2), "=r"(r3) : "r"(addr));
}
__device__ __forceinline__ void mma_bf16(float* d, uint32_t a0, uint32_t a1,
                                         uint32_t a2, uint32_t a3,
                                         uint32_t b0, uint32_t b1) {
    asm volatile(
        "mma.sync.aligned.m16n8k16.row.col.f32.bf16.bf16.f32 "
        "{%0,%1,%2,%3}, {%4,%5,%6,%7}, {%8,%9}, {%0,%1,%2,%3};"
        : "+f"(d[0]), "+f"(d[1]), "+f"(d[2]), "+f"(d[3])
        : "r"(a0), "r"(a1), "r"(a2), "r"(a3), "r"(b0), "r"(b1));
}
// split two floats into big/small bf16x2 (x -> .x/low lane)
__device__ __forceinline__ void split_pack(float x, float y, uint32_t& big, uint32_t& small) {
    __nv_bfloat16 bx = __float2bfloat16(x), by = __float2bfloat16(y);
    __nv_bfloat162 bb; bb.x = bx; bb.y = by;
    big = *reinterpret_cast<uint32_t*>(&bb);
    __nv_bfloat16 sx = __float2bfloat16(x - __bfloat162float(bx));
    __nv_bfloat16 sy = __float2bfloat16(y - __bfloat162float(by));
    __nv_bfloat162 ss; ss.x = sx; ss.y = sy;
    small = *reinterpret_cast<uint32_t*>(&ss);
}

// ---------------- split kernels ---------------------------------------------
__global__ void split_bf16_kernel(const float* __restrict__ in,
                                  __nv_bfloat16* __restrict__ big,
                                  __nv_bfloat16* __restrict__ small, int n)
{
    int i = blockIdx.x * blockDim.x + threadIdx.x;
    if (i >= n) return;
    float v = in[i];
    __nv_bfloat16 b = __float2bfloat16(v);
    big[i]   = b;
    small[i] = __float2bfloat16(v - __bfloat162float(b));
}

// W [K,N] row-major -> W^T big/small bf16 [N,K] row-major
__global__ void split_transpose_kernel(const float* __restrict__ W,
                                       __nv_bfloat16* __restrict__ bigT,
                                       __nv_bfloat16* __restrict__ smallT)
{
    __shared__ __nv_bfloat16 tb[32][33];
    __shared__ __nv_bfloat16 ts[32][33];
    int n0 = blockIdx.x * 32, k0 = blockIdx.y * 32;
#pragma unroll
    for (int rr = 0; rr < 4; rr++) {
        int r = threadIdx.y + rr * 8;
        float v = W[(size_t)(k0 + r) * DM + n0 + threadIdx.x];
        __nv_bfloat16 b = __float2bfloat16(v);
        tb[r][threadIdx.x] = b;
        ts[r][threadIdx.x] = __float2bfloat16(v - __bfloat162float(b));
    }
    __syncthreads();
#pragma unroll
    for (int rr = 0; rr < 4; rr++) {
        int r = threadIdx.y + rr * 8;   // output row (n)
        bigT  [(size_t)(n0 + r) * DM + k0 + threadIdx.x] = tb[threadIdx.x][r];
        smallT[(size_t)(n0 + r) * DM + k0 + threadIdx.x] = ts[threadIdx.x][r];
    }
}

// RoPE (dims 0..15) on Q,K then split Q,K,V into bf16 big/small
__global__ void rope_split_kernel(const float* __restrict__ Q, const float* __restrict__ K,
                                  const float* __restrict__ V,
                                  __nv_bfloat16* __restrict__ Qb, __nv_bfloat16* __restrict__ Qs,
                                  __nv_bfloat16* __restrict__ Kb, __nv_bfloat16* __restrict__ Ks,
                                  __nv_bfloat16* __restrict__ Vb, __nv_bfloat16* __restrict__ Vs)
{
    int idx = blockIdx.x * blockDim.x + threadIdx.x;
    if (idx >= BH*SEQ*DH) return;
    int row = idx >> 6, d = idx & 63, s = row & (SEQ - 1);
    size_t b0 = (size_t)row * DH;
    float qv, kv;
    if (d < 16) {
        int i = d & 7;
        float inv_freq = powf(10000.0f, -(float)i * 0.125f);
        float ang = (float)s * inv_freq;
        float c, sn; sincosf(ang, &sn, &c);
        float q1 = Q[b0+i], q2 = Q[b0+i+8];
        float k1 = K[b0+i], k2 = K[b0+i+8];
        if (d < 8) { qv = q1*c - q2*sn; kv = k1*c - k2*sn; }
        else       { qv = q1*sn + q2*c; kv = k1*sn + k2*c; }
    } else {
        qv = Q[b0+d]; kv = K[b0+d];
    }
    float vv = V[b0+d];
    __nv_bfloat16 t;
    t = __float2bfloat16(qv); Qb[idx] = t; Qs[idx] = __float2bfloat16(qv - __bfloat162float(t));
    t = __float2bfloat16(kv); Kb[idx] = t; Ks[idx] = __float2bfloat16(kv - __bfloat162float(t));
    t = __float2bfloat16(vv); Vb[idx] = t; Vs[idx] = __float2bfloat16(vv - __bfloat162float(t));
}

// ---------------- mma.sync bf16 GEMM (3xBF16) --------------------------------
#define BM 128
#define BN 128
#define KC 32
#define NCHUNK (DM/KC)

#define ROWB 80
#define TILE_B (128*ROWB)
#define OFF_AB 0
#define OFF_AS (1*TILE_B)
#define OFF_BB (2*TILE_B)
#define OFF_BS (3*TILE_B)
#define STAGE_B (4*TILE_B)        // 40960
#define GEMM_SMEM (2*STAGE_B)     // 81920

__device__ __forceinline__ void load_chunk(
    const __nv_bfloat16* __restrict__ Ab, const __nv_bfloat16* __restrict__ As,
    const __nv_bfloat16* __restrict__ Bb, const __nv_bfloat16* __restrict__ Bs,
    int m0, int n0, int k0, uint32_t buf, int tid)
{
    const __nv_bfloat16* srcs[4] = {
        Ab + (size_t)m0 * DM + k0,  As + (size_t)m0 * DM + k0,
        Bb + (size_t)n0 * DM + k0,  Bs + (size_t)n0 * DM + k0 };
    const uint32_t offs[4] = { OFF_AB, OFF_AS, OFF_BB, OFF_BS };
#pragma unroll
    for (int t = 0; t < 4; t++) {
#pragma unroll
        for (int i = 0; i < 2; i++) {
            int idx = i * 256 + tid;
            int row = idx >> 2, c = idx & 3;
            cp_async16(buf + offs[t] + row * ROWB + c * 16,
                       srcs[t] + (size_t)row * DM + c * 8);
        }
    }
}

template<int OUT_BHSD>
__global__ __launch_bounds__(256)
void gemm_mma(const __nv_bfloat16* __restrict__ Ab, const __nv_bfloat16* __restrict__ As,
              const __nv_bfloat16* __restrict__ Bb, const __nv_bfloat16* __restrict__ Bs,
              const float* __restrict__ bias, float* __restrict__ C)
{
    extern __shared__ char smem[];
    const uint32_t sbase = smem_u32(smem);
    const int tid  = threadIdx.x;
    const int wid  = tid >> 5;
    const int lane = tid & 31;
    const int warp_m = wid & 3;
    const int warp_n = wid >> 2;
    const int m0 = blockIdx.y * BM;
    const int n0 = blockIdx.x * BN;

    float acc[2][8][4];
#pragma unroll
    for (int i = 0; i < 2; i++)
#pragma unroll
        for (int j = 0; j < 8; j++)
#pragma unroll
            for (int t = 0; t < 4; t++) acc[i][j][t] = 0.f;

    const int a_r  = lane & 15;
    const int a_kh = (lane >> 4) * 8;
    const int b_g  = lane >> 3;
    const int b_lr = lane & 7;
    const int b_n  = (b_g >> 1) * 8 + b_lr;
    const int b_kh = (b_g & 1) * 8;

    load_chunk(Ab, As, Bb, Bs, m0, n0, 0,  sbase,           tid); CP_COMMIT();
    load_chunk(Ab, As, Bb, Bs, m0, n0, KC, sbase + STAGE_B, tid); CP_COMMIT();

    for (int c = 0; c < NCHUNK; c++) {
        CP_WAIT1();
        __syncthreads();
        const uint32_t buf = sbase + (uint32_t)(c & 1) * STAGE_B;

#pragma unroll
        for (int ks = 0; ks < 2; ks++) {
            const int k16 = ks * 16;
            uint32_t ab[2][4], asm_[2][4];
#pragma unroll
            for (int i = 0; i < 2; i++) {
                uint32_t arow = (uint32_t)(warp_m * 32 + i * 16 + a_r);
                uint32_t aoff = arow * ROWB + (uint32_t)((k16 + a_kh) >> 3) * 16;
                ldmx4(ab[i][0],  ab[i][1],  ab[i][2],  ab[i][3],  buf + OFF_AB + aoff);
                ldmx4(asm_[i][0], asm_[i][1], asm_[i][2], asm_[i][3], buf + OFF_AS + aoff);
            }
#pragma unroll
            for (int jp = 0; jp < 4; jp++) {
                uint32_t brow = (uint32_t)(warp_n * 64 + jp * 16 + b_n);
                uint32_t boff = brow * ROWB + (uint32_t)((k16 + b_kh) >> 3) * 16;
                uint32_t bb0, bb1, bb2, bb3, bs0, bs1, bs2, bs3;
                ldmx4(bb0, bb1, bb2, bb3, buf + OFF_BB + boff);
                ldmx4(bs0, bs1, bs2, bs3, buf + OFF_BS + boff);
#pragma unroll
                for (int i = 0; i < 2; i++) {
                    mma_bf16(acc[i][jp*2],   ab[i][0], ab[i][1], ab[i][2], ab[i][3], bb0, bb1);
                    mma_bf16(acc[i][jp*2],   ab[i][0], ab[i][1], ab[i][2], ab[i][3], bs0, bs1);
                    mma_bf16(acc[i][jp*2],   asm_[i][0], asm_[i][1], asm_[i][2], asm_[i][3], bb0, bb1);
                    mma_bf16(acc[i][jp*2+1], ab[i][0], ab[i][1], ab[i][2], ab[i][3], bb2, bb3);
                    mma_bf16(acc[i][jp*2+1], ab[i][0], ab[i][1], ab[i][2], ab[i][3], bs2, bs3);
                    mma_bf16(acc[i][jp*2+1], asm_[i][0], asm_[i][1], asm_[i][2], asm_[i][3], bb2, bb3);
                }
            }
        }
        __syncthreads();
        if (c + 2 < NCHUNK)
            load_chunk(Ab, As, Bb, Bs, m0, n0, (c + 2) * KC, buf, tid);
        CP_COMMIT();
    }

    const int gr = lane >> 2;
    const int tc = lane & 3;
#pragma unroll
    for (int i = 0; i < 2; i++) {
#pragma unroll
        for (int j = 0; j < 8; j++) {
            int col = n0 + warp_n * 64 + j * 8 + tc * 2;
            float b0 = __ldg(bias + col), b1 = __ldg(bias + col + 1);
#pragma unroll
            for (int h = 0; h < 2; h++) {
                int row = m0 + warp_m * 32 + i * 16 + gr + h * 8;
                float2 v = make_float2(acc[i][j][h*2] + b0, acc[i][j][h*2+1] + b1);
                if (OUT_BHSD) {
                    int bb = row >> 11, s = row & (SEQ - 1);
                    int hh = col >> 6,  d = col & (DH - 1);
                    *(float2*)(C + (((size_t)(bb * NH + hh)) * SEQ + s) * DH + d) = v;
                } else {
                    *(float2*)(C + (size_t)row * DM + col) = v;
                }
            }
        }
    }
}

// ---------------- mma.sync flash attention (compensated bf16) ----------------
// 128 queries/CTA, 64-key KV tiles, 8 warps (warp w owns query rows w*16..w*16+15).
// Padded 144B rows in smem for conflict-free ldmatrix.
#define AROWB 144u
#define A_QB  0u
#define A_QS  (128u*AROWB)            // 18432
#define A_ST0 (2u*128u*AROWB)         // 36864
#define A_KS  9216u
#define A_VB  18432u
#define A_VS  27648u
#define A_STAGE 36864u
#define ATTN_SMEM2 (A_ST0 + 2u*A_STAGE)   // 110592

__device__ __forceinline__ void attn_load_kv(
    const __nv_bfloat16* Kb, const __nv_bfloat16* Ks,
    const __nv_bfloat16* Vb, const __nv_bfloat16* Vs,
    size_t base, int n0, uint32_t stage, int tid)
{
#pragma unroll
    for (int i = 0; i < 2; i++) {
        int idx = i * 256 + tid;         // 0..511
        int row = idx >> 3, c = idx & 7;
        uint32_t so = stage + (uint32_t)row * AROWB + (uint32_t)c * 16;
        size_t   go = base + (size_t)(n0 + row) * DH + c * 8;
        cp_async16(so,          Kb + go);
        cp_async16(so + A_KS,   Ks + go);
        cp_async16(so + A_VB,   Vb + go);
        cp_async16(so + A_VS,   Vs + go);
    }
}

__global__ __launch_bounds__(256, 1)
void attn_mma(const __nv_bfloat16* __restrict__ Qb, const __nv_bfloat16* __restrict__ Qs,
              const __nv_bfloat16* __restrict__ Kb, const __nv_bfloat16* __restrict__ Ks,
              const __nv_bfloat16* __restrict__ Vb, const __nv_bfloat16* __restrict__ Vs,
              float* __restrict__ attn)
{
    extern __shared__ char smem[];
    const uint32_t sb = smem_u32(smem);
    const int tid = threadIdx.x, wid = tid >> 5, lane = tid & 31;
    const int bh = blockIdx.y;
    const int qt = (int)gridDim.x - 1 - (int)blockIdx.x;   // big tiles first
    const int m0 = qt * 128;
    const size_t base = (size_t)bh * SEQ * DH;
    const int ntiles = (m0 + 128) / 64;

    const int gr = lane >> 2, tc = lane & 3;
    // A-frag (Q / P) addressing
    const uint32_t a_row = (uint32_t)(wid * 16 + (lane & 15));
    const uint32_t a_kh16 = (uint32_t)((lane >> 4) * 16);      // bytes
    // B-frag (K) addressing
    const int b_g = lane >> 3, b_lr = lane & 7;
    const uint32_t k_nrow = (uint32_t)((b_g >> 1) * 8 + b_lr);
    const uint32_t k_kh16 = (uint32_t)((b_g & 1) * 16);        // bytes
    // V trans-frag addressing
    const uint32_t v_row = (uint32_t)((b_g & 1) * 8 + b_lr);
    const uint32_t v_col = (uint32_t)((b_g >> 1) * 16);        // bytes

    // ---- prologue loads: Q (both splits) + KV tile 0 -> group 0; KV tile 1 -> group 1
#pragma unroll
    for (int i = 0; i < 4; i++) {
        int idx = i * 256 + tid;         // 0..1023
        int row = idx >> 3, c = idx & 7;
        size_t go = base + (size_t)(m0 + row) * DH + c * 8;
        cp_async16(sb + A_QB + (uint32_t)row * AROWB + c * 16, Qb + go);
        cp_async16(sb + A_QS + (uint32_t)row * AROWB + c * 16, Qs + go);
    }
    attn_load_kv(Kb, Ks, Vb, Vs, base, 0, sb + A_ST0, tid);
    CP_COMMIT();
    if (ntiles > 1)
        attn_load_kv(Kb, Ks, Vb, Vs, base, 64, sb + A_ST0 + A_STAGE, tid);
    CP_COMMIT();

    float m_r[2] = { -1e30f, -1e30f };
    float l_r[2] = { 0.f, 0.f };
    float oa[8][4];
#pragma unroll
    for (int j = 0; j < 8; j++)
#pragma unroll
        for (int t = 0; t < 4; t++) oa[j][t] = 0.f;

    const int r0g = m0 + wid * 16 + gr;     // global query rows
    const int r1g = r0g + 8;

    for (int c = 0; c < ntiles; c++) {
        CP_WAIT1();
        __syncthreads();
        const uint32_t stg = sb + A_ST0 + (uint32_t)(c & 1) * A_STAGE;
        const int n0 = c * 64;

        // ---- S = Q K^T (3-term compensated) ----
        float sa[8][4];
#pragma unroll
        for (int j = 0; j < 8; j++)
#pragma unroll
            for (int t = 0; t < 4; t++) sa[j][t] = 0.f;

#pragma unroll
        for (int k16 = 0; k16 < 4; k16++) {
            uint32_t qoff = a_row * AROWB + (uint32_t)k16 * 32 + a_kh16;
            uint32_t qb0, qb1, qb2, qb3, qs0, qs1, qs2, qs3;
            ldmx4(qb0, qb1, qb2, qb3, sb + A_QB + qoff);
            ldmx4(qs0, qs1, qs2, qs3, sb + A_QS + qoff);
#pragma unroll
            for (int jp = 0; jp < 4; jp++) {
                uint32_t koff = ((uint32_t)(jp * 16) + k_nrow) * AROWB
                              + (uint32_t)k16 * 32 + k_kh16;
                uint32_t kb0, kb1, kb2, kb3, ks0, ks1, ks2, ks3;
                ldmx4(kb0, kb1, kb2, kb3, stg + koff);
                ldmx4(ks0, ks1, ks2, ks3, stg + A_KS + koff);
                mma_bf16(sa[jp*2],   qb0, qb1, qb2, qb3, kb0, kb1);
                mma_bf16(sa[jp*2],   qb0, qb1, qb2, qb3, ks0, ks1);
                mma_bf16(sa[jp*2],   qs0, qs1, qs2, qs3, kb0, kb1);
                mma_bf16(sa[jp*2+1], qb0, qb1, qb2, qb3, kb2, kb3);
                mma_bf16(sa[jp*2+1], qb0, qb1, qb2, qb3, ks2, ks3);
                mma_bf16(sa[jp*2+1], qs0, qs1, qs2, qs3, kb2, kb3);
            }
        }

        // ---- scale + causal mask ----
        const bool need_mask = (n0 + 63) > (m0 + wid * 16);
#pragma unroll
        for (int j = 0; j < 8; j++) {
            sa[j][0] *= 0.125f; sa[j][1] *= 0.125f;
            sa[j][2] *= 0.125f; sa[j][3] *= 0.125f;
        }
        if (need_mask) {
#pragma unroll
            for (int j = 0; j < 8; j++) {
                int cg = n0 + j * 8 + tc * 2;
                if (cg + 0 > r0g) sa[j][0] = -1e30f;
                if (cg + 1 > r0g) sa[j][1] = -1e30f;
                if (cg + 0 > r1g) sa[j][2] = -1e30f;
                if (cg + 1 > r1g) sa[j][3] = -1e30f;
            }
        }

        // ---- online softmax (rows r0, r1 per thread) ----
        float mx0 = -1e30f, mx1 = -1e30f;
#pragma unroll
        for (int j = 0; j < 8; j++) {
            mx0 = fmaxf(mx0, fmaxf(sa[j][0], sa[j][1]));
            mx1 = fmaxf(mx1, fmaxf(sa[j][2], sa[j][3]));
        }
        mx0 = fmaxf(mx0, __shfl_xor_sync(0xFFFFFFFFu, mx0, 1));
        mx0 = fmaxf(mx0, __shfl_xor_sync(0xFFFFFFFFu, mx0, 2));
        mx1 = fmaxf(mx1, __shfl_xor_sync(0xFFFFFFFFu, mx1, 1));
        mx1 = fmaxf(mx1, __shfl_xor_sync(0xFFFFFFFFu, mx1, 2));

        float mn0 = fmaxf(m_r[0], mx0), mn1 = fmaxf(m_r[1], mx1);
        float al0 = __expf(m_r[0] - mn0), al1 = __expf(m_r[1] - mn1);
        m_r[0] = mn0; m_r[1] = mn1;

        float sum0 = 0.f, sum1 = 0.f;
#pragma unroll
        for (int j = 0; j < 8; j++) {
            sa[j][0] = __expf(sa[j][0] - mn0);
            sa[j][1] = __expf(sa[j][1] - mn0);
            sa[j][2] = __expf(sa[j][2] - mn1);
            sa[j][3] = __expf(sa[j][3] - mn1);
            sum0 += sa[j][0] + sa[j][1];
            sum1 += sa[j][2] + sa[j][3];
        }
        l_r[0] = l_r[0] * al0 + sum0;     // partial per thread; quad-reduced at end
        l_r[1] = l_r[1] * al1 + sum1;

#pragma unroll
        for (int j = 0; j < 8; j++) {
            oa[j][0] *= al0; oa[j][1] *= al0;
            oa[j][2] *= al1; oa[j][3] *= al1;
        }

        // ---- O += P V (3-term compensated; P split in registers) ----
#pragma unroll
        for (int kc = 0; kc < 4; kc++) {
            uint32_t pb0, pb1, pb2, pb3, ps0, ps1, ps2, ps3;
            split_pack(sa[2*kc][0],   sa[2*kc][1],   pb0, ps0);
            split_pack(sa[2*kc][2],   sa[2*kc][3],   pb1, ps1);
            split_pack(sa[2*kc+1][0], sa[2*kc+1][1], pb2, ps2);
            split_pack(sa[2*kc+1][2], sa[2*kc+1][3], pb3, ps3);
#pragma unroll
            for (int dt = 0; dt < 4; dt++) {
                uint32_t voff = ((uint32_t)(kc * 16) + v_row) * AROWB
                              + (uint32_t)dt * 32 + v_col;
                uint32_t vb0, vb1, vb2, vb3, vs0, vs1, vs2, vs3;
                ldmx4t(vb0, vb1, vb2, vb3, stg + A_VB + voff);
                ldmx4t(vs0, vs1, vs2, vs3, stg + A_VS + voff);
                mma_bf16(oa[dt*2],   pb0, pb1, pb2, pb3, vb0, vb1);
                mma_bf16(oa[dt*2],   pb0, pb1, pb2, pb3, vs0, vs1);
                mma_bf16(oa[dt*2],   ps0, ps1, ps2, ps3, vb0, vb1);
                mma_bf16(oa[dt*2+1], pb0, pb1, pb2, pb3, vb2, vb3);
                mma_bf16(oa[dt*2+1], pb0, pb1, pb2, pb3, vs2, vs3);
                mma_bf16(oa[dt*2+1], ps0, ps1, ps2, ps3, vb2, vb3);
            }
        }

        __syncthreads();
        if (c + 2 < ntiles)
            attn_load_kv(Kb, Ks, Vb, Vs, base, (c + 2) * 64, stg, tid);
        CP_COMMIT();
    }

    // ---- epilogue: reduce l across quad, normalize, store ----
    float l0 = l_r[0], l1 = l_r[1];
    l0 += __shfl_xor_sync(0xFFFFFFFFu, l0, 1);
    l0 += __shfl_xor_sync(0xFFFFFFFFu, l0, 2);
    l1 += __shfl_xor_sync(0xFFFFFFFFu, l1, 1);
    l1 += __shfl_xor_sync(0xFFFFFFFFu, l1, 2);
    float inv0 = 1.f / l0, inv1 = 1.f / l1;

    const int b = bh >> 4, h = bh & 15;
#pragma unroll
    for (int j = 0; j < 8; j++) {
        int col = h * DH + j * 8 + tc * 2;
        *(float2*)(attn + ((size_t)(b * SEQ + r0g)) * DM + col) =
            make_float2(oa[j][0] * inv0, oa[j][1] * inv0);
        *(float2*)(attn + ((size_t)(b * SEQ + r1g)) * DM + col) =
            make_float2(oa[j][2] * inv1, oa[j][3] * inv1);
    }
}

// ---------------------------------------------------------------------------
extern "C" void kernel_launch(void* const* d_in, const int* in_sizes, int n_in,
                              void* d_out, int out_size)
{
    const float* x  = (const float*)d_in[0];
    const float* Wq = (const float*)d_in[1];
    const float* bq = (const float*)d_in[2];
    const float* Wk = (const float*)d_in[3];
    const float* bk = (const float*)d_in[4];
    const float* Wv = (const float*)d_in[5];
    const float* bv = (const float*)d_in[6];
    const float* Wo = (const float*)d_in[7];
    const float* bo = (const float*)d_in[8];
    float* out = (float*)d_out;

    float *Qp, *Kp, *Vp, *Ap;
    __nv_bfloat16 *xb, *xs, *ab, *as, *WbT, *WsT;
    __nv_bfloat16 *Qbp, *Qsp, *Kbp, *Ksp, *Vbp, *Vsp;
    cudaGetSymbolAddress((void**)&Qp, g_Q);
    cudaGetSymbolAddress((void**)&Kp, g_K);
    cudaGetSymbolAddress((void**)&Vp, g_V);
    cudaGetSymbolAddress((void**)&Ap, g_attn);
    cudaGetSymbolAddress((void**)&xb, g_xb);
    cudaGetSymbolAddress((void**)&xs, g_xs);
    cudaGetSymbolAddress((void**)&ab, g_ab);
    cudaGetSymbolAddress((void**)&as, g_as);
    cudaGetSymbolAddress((void**)&WbT, g_WbT);
    cudaGetSymbolAddress((void**)&WsT, g_WsT);
    cudaGetSymbolAddress((void**)&Qbp, g_Qb);
    cudaGetSymbolAddress((void**)&Qsp, g_Qs);
    cudaGetSymbolAddress((void**)&Kbp, g_Kb);
    cudaGetSymbolAddress((void**)&Ksp, g_Ks);
    cudaGetSymbolAddress((void**)&Vbp, g_Vb);
    cudaGetSymbolAddress((void**)&Vsp, g_Vs);

    cudaFuncSetAttribute(gemm_mma<0>,
                         cudaFuncAttributeMaxDynamicSharedMemorySize, GEMM_SMEM);
    cudaFuncSetAttribute(gemm_mma<1>,
                         cudaFuncAttributeMaxDynamicSharedMemorySize, GEMM_SMEM);
    cudaFuncSetAttribute(attn_mma,
                         cudaFuncAttributeMaxDynamicSharedMemorySize, (int)ATTN_SMEM2);

    const int WSZ = DM * DM;

    // input/weight splits
    split_bf16_kernel<<<(MTOT*DM + 255)/256, 256>>>(x, xb, xs, MTOT*DM);
    dim3 tgrid(DM/32, DM/32), tblk(32, 8);
    split_transpose_kernel<<<tgrid, tblk>>>(Wq, WbT + 0*WSZ, WsT + 0*WSZ);
    split_transpose_kernel<<<tgrid, tblk>>>(Wk, WbT + 1*WSZ, WsT + 1*WSZ);
    split_transpose_kernel<<<tgrid, tblk>>>(Wv, WbT + 2*WSZ, WsT + 2*WSZ);
    split_transpose_kernel<<<tgrid, tblk>>>(Wo, WbT + 3*WSZ, WsT + 3*WSZ);

    // projections (mma.sync bf16, 3xBF16)
    dim3 ggrid(DM/BN, MTOT/BM);   // (8, 32)
    gemm_mma<1><<<ggrid, 256, GEMM_SMEM>>>(xb, xs, WbT + 0*WSZ, WsT + 0*WSZ, bq, Qp);
    gemm_mma<1><<<ggrid, 256, GEMM_SMEM>>>(xb, xs, WbT + 1*WSZ, WsT + 1*WSZ, bk, Kp);
    gemm_mma<1><<<ggrid, 256, GEMM_SMEM>>>(xb, xs, WbT + 2*WSZ, WsT + 2*WSZ, bv, Vp);

    // RoPE + bf16 splits of Q,K,V
    rope_split_kernel<<<(BH*SEQ*DH + 255)/256, 256>>>(Qp, Kp, Vp,
                                                      Qbp, Qsp, Kbp, Ksp, Vbp, Vsp);

    // tensor-core flash attention
    attn_mma<<<dim3(SEQ/128, BH), 256, ATTN_SMEM2>>>(Qbp, Qsp, Kbp, Ksp, Vbp, Vsp, Ap);

    // output projection
    split_bf16_kernel<<<(MTOT*DM + 255)/256, 256>>>(Ap, ab, as, MTOT*DM);
    gemm_mma<0><<<ggrid, 256, GEMM_SMEM>>>(ab, as, WbT + 3*WSZ, WsT + 3*WSZ, bo, out);
}